// round 9
// baseline (speedup 1.0000x reference)
#include <cuda_runtime.h>
#include <math.h>

typedef unsigned long long u64;

__device__ __forceinline__ u64 pk2(float lo, float hi) {
    u64 r; asm("mov.b64 %0, {%1, %2};" : "=l"(r) : "f"(lo), "f"(hi)); return r;
}
__device__ __forceinline__ void upk2(u64 v, float& lo, float& hi) {
    asm("mov.b64 {%0, %1}, %2;" : "=f"(lo), "=f"(hi) : "l"(v));
}
// packed fp32x2 FMA (Blackwell): d = a*b + c on both 32-bit lanes
__device__ __forceinline__ u64 fma2(u64 a, u64 b, u64 c) {
    u64 d; asm("fma.rn.f32x2 %0, %1, %2, %3;" : "=l"(d) : "l"(a), "l"(b), "l"(c)); return d;
}
__device__ __forceinline__ float gelu_f(float x) {
    return 0.5f * x * (1.0f + erff(x * 0.70710678118654752440f));
}

// ---- Transposed weight scratch (coalesced columns) ----
__device__ float g_w1T[128 * 256];   // w1T[d][f]  = w1[f][d]
__device__ float g_w2T[256 * 128];   // w2T[f][d]  = w2[d][f]
__device__ float g_hw1T[256 * 256];  // hw1T[c][f] = hw1[f][c]
// ---- Inter-kernel scratch ----
#define MAXQ 32768
__device__ float g_pooled[MAXQ * 256];
__device__ float g_mu[MAXQ];
__device__ float g_sig[MAXQ];

__global__ void __launch_bounds__(256)
transpose_weights(const float* __restrict__ w1, const float* __restrict__ w2,
                  const float* __restrict__ hw1)
{
    int i = blockIdx.x * blockDim.x + threadIdx.x;   // 0 .. 65535
    if (i < 256 * 128) {
        int f = i >> 7, d = i & 127;
        g_w1T[d * 256 + f] = w1[i];      // w1 [256][128]
        int d2 = i >> 8, f2 = i & 255;
        g_w2T[f2 * 128 + d2] = w2[i];    // w2 [128][256]
    }
    if (i < 256 * 256) {
        int f = i >> 8, c = i & 255;
        g_hw1T[c * 256 + f] = hw1[i];    // hw1 [256][256]
    }
}

#define HT 36  // row stride (floats): 144B, 16B-aligned, conflict-padded

// Dynamic SMEM layout (floats):
//   [0      , 4608 )  hT   [128][36]  (token-MLP hidden; reused as w2 stage + pool partials)
//   [4608   , 13824)  x2T  [256][36]  (expanded hidden, f-major)
//   [13824  , 13952)  tok  [32][4]
//   [13952  , 14080)  ln1_g
//   [14080  , 14208)  ln1_b
//   [14208  , 14240)  sc
#define SMEM_FLOATS 14240
#define SMEM_BYTES  (SMEM_FLOATS * 4)

__global__ void __launch_bounds__(128, 4)
ff_body_kernel(const float* __restrict__ xyt_q, const float* __restrict__ obs_coords,
               const float* __restrict__ obs_vals, const int* __restrict__ nb_idx,
               const float* __restrict__ log_gammas,
               const float* __restrict__ w_in, const float* __restrict__ b_in,
               const float* __restrict__ ln1_g, const float* __restrict__ ln1_b,
               const float* __restrict__ b1, const float* __restrict__ b2)
{
    extern __shared__ float sm[];
    float* sm_hT   = sm;
    float* sm_x2T  = sm + 4608;
    float* sm_tok  = sm + 13824;
    float* sm_g    = sm + 13952;
    float* sm_b    = sm + 14080;
    float* sm_sc   = sm + 14208;

    const int t    = threadIdx.x;
    const int q    = blockIdx.x;
    const int lane = t & 31;
    const int wid  = t >> 5;

    // ---- Phase 0a: preload LN1 params + query coords/gammas ----
    sm_g[t] = ln1_g[t];
    sm_b[t] = ln1_b[t];
    if (t < 3) {
        sm_sc[4 + t] = xyt_q[q * 3 + t];
        sm_sc[8 + t] = expf(log_gammas[t]);
    }
    __syncthreads();

    // ---- Phase 0b: gather neighbors, mu/sigma, build tokens (warp 0) ----
    if (t < 32) {
        int idx  = nb_idx[q * 32 + t];
        float cx = obs_coords[idx * 3 + 0];
        float cy = obs_coords[idx * 3 + 1];
        float cz = obs_coords[idx * 3 + 2];
        float v  = obs_vals[idx];
        float s = v, s2 = v * v;
        #pragma unroll
        for (int o = 16; o; o >>= 1) {
            s  += __shfl_xor_sync(0xffffffffu, s,  o);
            s2 += __shfl_xor_sync(0xffffffffu, s2, o);
        }
        float mu   = s * (1.0f / 32.0f);
        float varu = fmaxf((s2 - s * mu) * (1.0f / 31.0f), 0.0f);  // unbiased (ddof=1)
        float sig  = fmaxf(sqrtf(varu), 1e-3f);
        if (t == 0) { sm_sc[0] = mu; sm_sc[1] = sig; g_mu[q] = mu; g_sig[q] = sig; }
        float4 tk;
        tk.x = (cx - sm_sc[4]) * sm_sc[8];
        tk.y = (cy - sm_sc[5]) * sm_sc[9];
        tk.z = (cz - sm_sc[6]) * sm_sc[10];
        tk.w = (v - mu) / sig;
        ((float4*)sm_tok)[t] = tk;
    }
    __syncthreads();

    // ---- Phase 1: h[k][d] = gelu(tokens @ w_in^T + b_in); thread = channel d ----
    {
        float4 wv = ((const float4*)w_in)[t];
        float  bw = b_in[t];
        float* hrow = sm_hT + t * HT;
        #pragma unroll
        for (int k = 0; k < 32; k++) {
            float4 tk = ((const float4*)sm_tok)[k];
            float a = fmaf(tk.w, wv.w, fmaf(tk.z, wv.z, fmaf(tk.y, wv.y, fmaf(tk.x, wv.x, bw))));
            hrow[k] = gelu_f(a);
        }
    }
    __syncthreads();

    // ---- Phase 2: LayerNorm over D per token (warp per 8 tokens), in-place ----
    {
        #pragma unroll
        for (int kk = 0; kk < 8; kk++) {
            int k = wid * 8 + kk;
            float x0 = sm_hT[(lane      ) * HT + k];
            float x1 = sm_hT[(lane + 32 ) * HT + k];
            float x2 = sm_hT[(lane + 64 ) * HT + k];
            float x3 = sm_hT[(lane + 96 ) * HT + k];
            float s  = x0 + x1 + x2 + x3;
            float s2 = x0*x0 + x1*x1 + x2*x2 + x3*x3;
            #pragma unroll
            for (int o = 16; o; o >>= 1) {
                s  += __shfl_xor_sync(0xffffffffu, s,  o);
                s2 += __shfl_xor_sync(0xffffffffu, s2, o);
            }
            float m   = s * (1.0f / 128.0f);
            float inv = rsqrtf(s2 * (1.0f / 128.0f) - m * m + 1e-5f);
            sm_hT[(lane      ) * HT + k] = (x0 - m) * inv * sm_g[lane      ] + sm_b[lane      ];
            sm_hT[(lane + 32 ) * HT + k] = (x1 - m) * inv * sm_g[lane + 32 ] + sm_b[lane + 32 ];
            sm_hT[(lane + 64 ) * HT + k] = (x2 - m) * inv * sm_g[lane + 64 ] + sm_b[lane + 64 ];
            sm_hT[(lane + 96 ) * HT + k] = (x3 - m) * inv * sm_g[lane + 96 ] + sm_b[lane + 96 ];
        }
    }
    __syncthreads();

    // ---- Phase 3: x2[k][f] = gelu(xn @ w1^T + b1) ----
    // Thread: features {2a, 2a+1, 128+2a, 129+2a} (a = t&63), token half h = t>>6.
    {
        const int a = t & 63;
        const int h = t >> 6;
        float2 bb0 = ((const float2*)b1)[a];
        float2 bb1 = ((const float2*)b1)[a + 64];
        u64 acc[4][8];
        #pragma unroll
        for (int j = 0; j < 8; j++) {
            acc[0][j] = pk2(bb0.x, bb0.x);
            acc[1][j] = pk2(bb0.y, bb0.y);
            acc[2][j] = pk2(bb1.x, bb1.x);
            acc[3][j] = pk2(bb1.y, bb1.y);
        }
        #pragma unroll 4
        for (int d = 0; d < 128; d++) {
            float2 w0 = ((const float2*)(g_w1T + (d << 8)      ))[a];
            float2 w1v= ((const float2*)(g_w1T + (d << 8) + 128))[a];
            u64 wp0 = pk2(w0.x, w0.x);
            u64 wp1 = pk2(w0.y, w0.y);
            u64 wp2 = pk2(w1v.x, w1v.x);
            u64 wp3 = pk2(w1v.y, w1v.y);
            const ulonglong2* xr = (const ulonglong2*)(sm_hT + d * HT + 16 * h);
            #pragma unroll
            for (int i = 0; i < 4; i++) {
                ulonglong2 xp = xr[i];   // tokens 16h+4i .. 16h+4i+3
                acc[0][2*i  ] = fma2(xp.x, wp0, acc[0][2*i  ]);
                acc[0][2*i+1] = fma2(xp.y, wp0, acc[0][2*i+1]);
                acc[1][2*i  ] = fma2(xp.x, wp1, acc[1][2*i  ]);
                acc[1][2*i+1] = fma2(xp.y, wp1, acc[1][2*i+1]);
                acc[2][2*i  ] = fma2(xp.x, wp2, acc[2][2*i  ]);
                acc[2][2*i+1] = fma2(xp.y, wp2, acc[2][2*i+1]);
                acc[3][2*i  ] = fma2(xp.x, wp3, acc[3][2*i  ]);
                acc[3][2*i+1] = fma2(xp.y, wp3, acc[3][2*i+1]);
            }
        }
        int feat[4] = {2*a, 2*a + 1, 128 + 2*a, 129 + 2*a};
        #pragma unroll
        for (int ftr = 0; ftr < 4; ftr++) {
            float2* orow = (float2*)(sm_x2T + feat[ftr] * HT + 16 * h);
            #pragma unroll
            for (int j = 0; j < 8; j++) {
                float lo, hi; upk2(acc[ftr][j], lo, hi);
                orow[j] = make_float2(gelu_f(lo), gelu_f(hi));
            }
        }
    }
    __syncthreads();   // phase3 done: sm_hT is now dead -> reuse as w2 stage buffer

    // ---- Phase 4: h2[k][d] = gelu(x2 @ w2^T + b2) + partial pools ----
    // w2 staged through SMEM in 8 chunks of 32 f-rows (16KB): each weight
    // fetched from L2 exactly ONCE per CTA (was 4x redundant LDG).
    {
        const int l = lane;
        float2 bb0 = ((const float2*)b2)[l];
        float2 bb1 = ((const float2*)b2)[l + 32];
        u64 acc[4][4];
        #pragma unroll
        for (int j = 0; j < 4; j++) {
            acc[0][j] = pk2(bb0.x, bb0.x);
            acc[1][j] = pk2(bb0.y, bb0.y);
            acc[2][j] = pk2(bb1.x, bb1.x);
            acc[3][j] = pk2(bb1.y, bb1.y);
        }
        float*  sm_ws  = sm_hT;                    // 4096 floats = 16KB stage
        float4* sm_ws4 = (float4*)sm_ws;
        const float4* w2T4 = (const float4*)g_w2T;

        for (int c = 0; c < 8; c++) {
            if (c) __syncthreads();                // prior chunk fully consumed
            #pragma unroll
            for (int j = 0; j < 8; j++)            // coalesced: 1024 float4 per chunk
                sm_ws4[j * 128 + t] = w2T4[c * 1024 + j * 128 + t];
            __syncthreads();

            #pragma unroll 4
            for (int fi = 0; fi < 32; fi++) {
                int f = c * 32 + fi;
                float2 w0 = ((const float2*)(sm_ws + fi * 128     ))[l];
                float2 w1v= ((const float2*)(sm_ws + fi * 128 + 64))[l];
                u64 wp0 = pk2(w0.x, w0.x);
                u64 wp1 = pk2(w0.y, w0.y);
                u64 wp2 = pk2(w1v.x, w1v.x);
                u64 wp3 = pk2(w1v.y, w1v.y);
                const ulonglong2* xr = (const ulonglong2*)(sm_x2T + f * HT + 8 * wid);
                #pragma unroll
                for (int i = 0; i < 2; i++) {
                    ulonglong2 xp = xr[i];   // tokens 8wid+4i .. +3
                    acc[0][2*i  ] = fma2(xp.x, wp0, acc[0][2*i  ]);
                    acc[0][2*i+1] = fma2(xp.y, wp0, acc[0][2*i+1]);
                    acc[1][2*i  ] = fma2(xp.x, wp1, acc[1][2*i  ]);
                    acc[1][2*i+1] = fma2(xp.y, wp1, acc[1][2*i+1]);
                    acc[2][2*i  ] = fma2(xp.x, wp2, acc[2][2*i  ]);
                    acc[2][2*i+1] = fma2(xp.y, wp2, acc[2][2*i+1]);
                    acc[3][2*i  ] = fma2(xp.x, wp3, acc[3][2*i  ]);
                    acc[3][2*i+1] = fma2(xp.y, wp3, acc[3][2*i+1]);
                }
            }
        }
        __syncthreads();    // last chunk consumed everywhere before reusing sm_hT

        // gelu + partial pools over this thread's 8 tokens, per feature
        int dfeat[4] = {2*l, 2*l + 1, 64 + 2*l, 65 + 2*l};
        float* sm_ps = sm_hT;          // [4][128] partial sums
        float* sm_pm = sm_hT + 512;    // [4][128] partial maxes
        #pragma unroll
        for (int ftr = 0; ftr < 4; ftr++) {
            float ps = 0.0f, pm = -INFINITY;
            #pragma unroll
            for (int j = 0; j < 4; j++) {
                float lo, hi; upk2(acc[ftr][j], lo, hi);
                float g0 = gelu_f(lo), g1 = gelu_f(hi);
                ps += g0 + g1;
                pm = fmaxf(pm, fmaxf(g0, g1));
            }
            sm_ps[wid * 128 + dfeat[ftr]] = ps;
            sm_pm[wid * 128 + dfeat[ftr]] = pm;
        }
    }
    __syncthreads();

    // ---- Phase 4b: reduce partials, write pooled to global ----
    {
        float* sm_ps = sm_hT;
        float* sm_pm = sm_hT + 512;
        float s  = sm_ps[t] + sm_ps[128 + t] + sm_ps[256 + t] + sm_ps[384 + t];
        float mx = fmaxf(fmaxf(sm_pm[t], sm_pm[128 + t]), fmaxf(sm_pm[256 + t], sm_pm[384 + t]));
        g_pooled[(size_t)q * 256 + t]       = s * (1.0f / 32.0f);
        g_pooled[(size_t)q * 256 + 128 + t] = mx;
    }
}

// ================= Head kernel: LN(256) + Lin(256,256)+gelu + Lin(256,1) ==========
// One CTA = 32 queries, 256 threads (thread = output feature for the GEMM).
#define K2P 36
__global__ void __launch_bounds__(256)
ff_head_kernel(const float* __restrict__ hln_g, const float* __restrict__ hln_b,
               const float* __restrict__ hb1, const float* __restrict__ hw2,
               const float* __restrict__ hb2, int Q, float* __restrict__ out)
{
    __shared__ float s_pnT[256 * K2P];   // [k][q'] normalized pooled, transposed
    __shared__ float s_hg[256];
    __shared__ float s_hb[256];

    const int t    = threadIdx.x;
    const int lane = t & 31;
    const int w8   = t >> 5;          // warp 0..7
    const int qb   = blockIdx.x * 32;

    s_hg[t] = hln_g[t];
    s_hb[t] = hln_b[t];
    __syncthreads();

    // ---- LN per query (warp per query, 4 queries per warp) ----
    #pragma unroll
    for (int it = 0; it < 4; it++) {
        int qq = w8 * 4 + it;         // 0..31
        int q  = qb + qq;
        if (q < Q) {
            const float* row = g_pooled + (size_t)q * 256;
            float x[8];
            float s = 0.0f, s2 = 0.0f;
            #pragma unroll
            for (int j = 0; j < 8; j++) {
                x[j] = row[lane + 32 * j];
                s += x[j]; s2 += x[j] * x[j];
            }
            #pragma unroll
            for (int o = 16; o; o >>= 1) {
                s  += __shfl_xor_sync(0xffffffffu, s,  o);
                s2 += __shfl_xor_sync(0xffffffffu, s2, o);
            }
            float m   = s * (1.0f / 256.0f);
            float inv = rsqrtf(s2 * (1.0f / 256.0f) - m * m + 1e-5f);
            #pragma unroll
            for (int j = 0; j < 8; j++) {
                int k = lane + 32 * j;
                s_pnT[k * K2P + qq] = (x[j] - m) * inv * s_hg[k] + s_hb[k];
            }
        }
    }
    __syncthreads();

    // ---- GEMM: p[qq][f=t] = gelu( sum_k pn[qq][k] * hw1T[k][t] + hb1[t] ) ----
    u64 acc[16];
    #pragma unroll
    for (int j = 0; j < 16; j++) acc[j] = 0ull;
    #pragma unroll 2
    for (int k = 0; k < 256; k++) {
        float w = g_hw1T[(k << 8) + t];      // coalesced
        u64 wp = pk2(w, w);
        const ulonglong2* xr = (const ulonglong2*)(s_pnT + k * K2P);
        #pragma unroll
        for (int i = 0; i < 8; i++) {
            ulonglong2 xp = xr[i];           // queries 4i..4i+3 (broadcast)
            acc[2*i  ] = fma2(xp.x, wp, acc[2*i  ]);
            acc[2*i+1] = fma2(xp.y, wp, acc[2*i+1]);
        }
    }
    float hb = hb1[t];
    float ws = hw2[t];
    float v[32];
    #pragma unroll
    for (int j = 0; j < 16; j++) {
        float lo, hi; upk2(acc[j], lo, hi);
        v[2*j]   = gelu_f(lo + hb) * ws;
        v[2*j+1] = gelu_f(hi + hb) * ws;
    }
    __syncthreads();                          // all s_pnT reads done
    // scatter contributions: row f = t, col q'
    #pragma unroll
    for (int j = 0; j < 32; j++) s_pnT[t * K2P + j] = v[j];
    __syncthreads();

    // ---- final reduction over 256 features per query ----
    {
        int qq = t >> 3;          // query 0..31
        int c8 = t & 7;           // chunk 0..7 (32 features each)
        float ps = 0.0f;
        #pragma unroll 8
        for (int j = 0; j < 32; j++)
            ps += s_pnT[(c8 * 32 + j) * K2P + qq];
        ps += __shfl_xor_sync(0xffffffffu, ps, 1);
        ps += __shfl_xor_sync(0xffffffffu, ps, 2);
        ps += __shfl_xor_sync(0xffffffffu, ps, 4);
        if (c8 == 0) {
            int q = qb + qq;
            if (q < Q)
                out[q] = (ps + hb2[0]) * g_sig[q] + g_mu[q];
        }
    }
}

extern "C" void kernel_launch(void* const* d_in, const int* in_sizes, int n_in,
                              void* d_out, int out_size)
{
    const float* xyt_q      = (const float*)d_in[0];
    const float* obs_coords = (const float*)d_in[1];
    const float* obs_vals   = (const float*)d_in[2];
    const int*   nb_idx     = (const int*  )d_in[3];
    const float* log_gammas = (const float*)d_in[4];
    const float* w_in       = (const float*)d_in[5];
    const float* b_in       = (const float*)d_in[6];
    const float* ln1_g      = (const float*)d_in[7];
    const float* ln1_b      = (const float*)d_in[8];
    const float* w1         = (const float*)d_in[9];
    const float* b1         = (const float*)d_in[10];
    const float* w2         = (const float*)d_in[11];
    const float* b2         = (const float*)d_in[12];
    const float* hln_g      = (const float*)d_in[13];
    const float* hln_b      = (const float*)d_in[14];
    const float* hw1        = (const float*)d_in[15];
    const float* hb1        = (const float*)d_in[16];
    const float* hw2        = (const float*)d_in[17];
    const float* hb2        = (const float*)d_in[18];
    float* out = (float*)d_out;

    int Q = in_sizes[0] / 3;   // xyt_q is [Q,3]

    transpose_weights<<<256, 256>>>(w1, w2, hw1);

    cudaFuncSetAttribute(ff_body_kernel,
                         cudaFuncAttributeMaxDynamicSharedMemorySize, SMEM_BYTES);

    ff_body_kernel<<<Q, 128, SMEM_BYTES>>>(
        xyt_q, obs_coords, obs_vals, nb_idx, log_gammas,
        w_in, b_in, ln1_g, ln1_b, b1, b2);

    ff_head_kernel<<<(Q + 31) / 32, 256>>>(hln_g, hln_b, hb1, hw2, hb2, Q, out);
}

// round 11
// speedup vs baseline: 1.7048x; 1.7048x over previous
#include <cuda_runtime.h>
#include <math.h>

typedef unsigned long long u64;

__device__ __forceinline__ u64 pk2(float lo, float hi) {
    u64 r; asm("mov.b64 %0, {%1, %2};" : "=l"(r) : "f"(lo), "f"(hi)); return r;
}
__device__ __forceinline__ void upk2(u64 v, float& lo, float& hi) {
    asm("mov.b64 {%0, %1}, %2;" : "=f"(lo), "=f"(hi) : "l"(v));
}
// packed fp32x2 FMA (Blackwell): d = a*b + c on both 32-bit lanes
__device__ __forceinline__ u64 fma2(u64 a, u64 b, u64 c) {
    u64 d; asm("fma.rn.f32x2 %0, %1, %2, %3;" : "=l"(d) : "l"(a), "l"(b), "l"(c)); return d;
}
__device__ __forceinline__ float gelu_f(float x) {
    return 0.5f * x * (1.0f + erff(x * 0.70710678118654752440f));
}

// ---- Transposed weight scratch (coalesced columns; 16B-aligned for float4) ----
__device__ __align__(16) float g_w1T[128 * 256];   // w1T[d][f]  = w1[f][d]
__device__ __align__(16) float g_w2T[256 * 128];   // w2T[f][d]  = w2[d][f]
__device__ __align__(16) float g_hw1T[256 * 256];  // hw1T[c][f] = hw1[f][c]
// ---- Inter-kernel scratch ----
#define MAXQ 32768
__device__ __align__(16) float g_pooled[MAXQ * 256];
__device__ float g_mu[MAXQ];
__device__ float g_sig[MAXQ];

__global__ void __launch_bounds__(256)
transpose_weights(const float* __restrict__ w1, const float* __restrict__ w2,
                  const float* __restrict__ hw1)
{
    int i = blockIdx.x * blockDim.x + threadIdx.x;   // 0 .. 65535
    if (i < 256 * 128) {
        int f = i >> 7, d = i & 127;
        g_w1T[d * 256 + f] = w1[i];      // w1 [256][128]
        int d2 = i >> 8, f2 = i & 255;
        g_w2T[f2 * 128 + d2] = w2[i];    // w2 [128][256]
    }
    if (i < 256 * 256) {
        int f = i >> 8, c = i & 255;
        g_hw1T[c * 256 + f] = hw1[i];    // hw1 [256][256]
    }
}

#define HT 36  // row stride (floats): 144B, 16B-aligned, conflict-padded

// Dynamic SMEM layout (floats):
//   [0      , 4608 )  hT   [128][36]  (token-MLP hidden; reused as pool partials)
//   [4608   , 13824)  x2T  [256][36]  (expanded hidden, f-major)
//   [13824  , 13952)  tok  [32][4]
//   [13952  , 14080)  ln1_g
//   [14080  , 14208)  ln1_b
//   [14208  , 14240)  sc
#define SMEM_FLOATS 14240
#define SMEM_BYTES  (SMEM_FLOATS * 4)

__global__ void __launch_bounds__(128, 4)
ff_body_kernel(const float* __restrict__ xyt_q, const float* __restrict__ obs_coords,
               const float* __restrict__ obs_vals, const int* __restrict__ nb_idx,
               const float* __restrict__ log_gammas,
               const float* __restrict__ w_in, const float* __restrict__ b_in,
               const float* __restrict__ ln1_g, const float* __restrict__ ln1_b,
               const float* __restrict__ b1, const float* __restrict__ b2)
{
    extern __shared__ float sm[];
    float* sm_hT   = sm;
    float* sm_x2T  = sm + 4608;
    float* sm_tok  = sm + 13824;
    float* sm_g    = sm + 13952;
    float* sm_b    = sm + 14080;
    float* sm_sc   = sm + 14208;

    const int t    = threadIdx.x;
    const int q    = blockIdx.x;
    const int lane = t & 31;
    const int wid  = t >> 5;

    // ---- Phase 0a: preload LN1 params + query coords/gammas ----
    sm_g[t] = ln1_g[t];
    sm_b[t] = ln1_b[t];
    if (t < 3) {
        sm_sc[4 + t] = xyt_q[q * 3 + t];
        sm_sc[8 + t] = expf(log_gammas[t]);
    }
    __syncthreads();

    // ---- Phase 0b: gather neighbors, mu/sigma, build tokens (warp 0) ----
    if (t < 32) {
        int idx  = nb_idx[q * 32 + t];
        float cx = obs_coords[idx * 3 + 0];
        float cy = obs_coords[idx * 3 + 1];
        float cz = obs_coords[idx * 3 + 2];
        float v  = obs_vals[idx];
        float s = v, s2 = v * v;
        #pragma unroll
        for (int o = 16; o; o >>= 1) {
            s  += __shfl_xor_sync(0xffffffffu, s,  o);
            s2 += __shfl_xor_sync(0xffffffffu, s2, o);
        }
        float mu   = s * (1.0f / 32.0f);
        float varu = fmaxf((s2 - s * mu) * (1.0f / 31.0f), 0.0f);  // unbiased (ddof=1)
        float sig  = fmaxf(sqrtf(varu), 1e-3f);
        if (t == 0) { sm_sc[0] = mu; sm_sc[1] = sig; g_mu[q] = mu; g_sig[q] = sig; }
        float4 tk;
        tk.x = (cx - sm_sc[4]) * sm_sc[8];
        tk.y = (cy - sm_sc[5]) * sm_sc[9];
        tk.z = (cz - sm_sc[6]) * sm_sc[10];
        tk.w = (v - mu) / sig;
        ((float4*)sm_tok)[t] = tk;
    }
    __syncthreads();

    // ---- Phase 1: h[k][d] = gelu(tokens @ w_in^T + b_in); thread = channel d ----
    {
        float4 wv = ((const float4*)w_in)[t];
        float  bw = b_in[t];
        float* hrow = sm_hT + t * HT;
        #pragma unroll
        for (int k = 0; k < 32; k++) {
            float4 tk = ((const float4*)sm_tok)[k];
            float a = fmaf(tk.w, wv.w, fmaf(tk.z, wv.z, fmaf(tk.y, wv.y, fmaf(tk.x, wv.x, bw))));
            hrow[k] = gelu_f(a);
        }
    }
    __syncthreads();

    // ---- Phase 2: LayerNorm over D per token (warp per 8 tokens), in-place ----
    {
        #pragma unroll
        for (int kk = 0; kk < 8; kk++) {
            int k = wid * 8 + kk;
            float x0 = sm_hT[(lane      ) * HT + k];
            float x1 = sm_hT[(lane + 32 ) * HT + k];
            float x2 = sm_hT[(lane + 64 ) * HT + k];
            float x3 = sm_hT[(lane + 96 ) * HT + k];
            float s  = x0 + x1 + x2 + x3;
            float s2 = x0*x0 + x1*x1 + x2*x2 + x3*x3;
            #pragma unroll
            for (int o = 16; o; o >>= 1) {
                s  += __shfl_xor_sync(0xffffffffu, s,  o);
                s2 += __shfl_xor_sync(0xffffffffu, s2, o);
            }
            float m   = s * (1.0f / 128.0f);
            float inv = rsqrtf(s2 * (1.0f / 128.0f) - m * m + 1e-5f);
            sm_hT[(lane      ) * HT + k] = (x0 - m) * inv * sm_g[lane      ] + sm_b[lane      ];
            sm_hT[(lane + 32 ) * HT + k] = (x1 - m) * inv * sm_g[lane + 32 ] + sm_b[lane + 32 ];
            sm_hT[(lane + 64 ) * HT + k] = (x2 - m) * inv * sm_g[lane + 64 ] + sm_b[lane + 64 ];
            sm_hT[(lane + 96 ) * HT + k] = (x3 - m) * inv * sm_g[lane + 96 ] + sm_b[lane + 96 ];
        }
    }
    __syncthreads();

    // ---- Phase 3: x2[k][f] = gelu(xn @ w1^T + b1) ----
    // Thread: 4 CONSECUTIVE features {4a..4a+3} (a = t&63), token half h = t>>6.
    // Weight fetch = one LDG.128 per d (was 2x LDG.64): half the L1tex instr.
    {
        const int a = t & 63;
        const int h = t >> 6;
        float4 bb = ((const float4*)b1)[a];
        u64 acc[4][8];
        #pragma unroll
        for (int j = 0; j < 8; j++) {
            acc[0][j] = pk2(bb.x, bb.x);
            acc[1][j] = pk2(bb.y, bb.y);
            acc[2][j] = pk2(bb.z, bb.z);
            acc[3][j] = pk2(bb.w, bb.w);
        }
        #pragma unroll 4
        for (int d = 0; d < 128; d++) {
            float4 w = ((const float4*)(g_w1T + (d << 8)))[a];   // feats 4a..4a+3
            u64 wp0 = pk2(w.x, w.x);
            u64 wp1 = pk2(w.y, w.y);
            u64 wp2 = pk2(w.z, w.z);
            u64 wp3 = pk2(w.w, w.w);
            const ulonglong2* xr = (const ulonglong2*)(sm_hT + d * HT + 16 * h);
            #pragma unroll
            for (int i = 0; i < 4; i++) {
                ulonglong2 xp = xr[i];   // tokens 16h+4i .. 16h+4i+3
                acc[0][2*i  ] = fma2(xp.x, wp0, acc[0][2*i  ]);
                acc[0][2*i+1] = fma2(xp.y, wp0, acc[0][2*i+1]);
                acc[1][2*i  ] = fma2(xp.x, wp1, acc[1][2*i  ]);
                acc[1][2*i+1] = fma2(xp.y, wp1, acc[1][2*i+1]);
                acc[2][2*i  ] = fma2(xp.x, wp2, acc[2][2*i  ]);
                acc[2][2*i+1] = fma2(xp.y, wp2, acc[2][2*i+1]);
                acc[3][2*i  ] = fma2(xp.x, wp3, acc[3][2*i  ]);
                acc[3][2*i+1] = fma2(xp.y, wp3, acc[3][2*i+1]);
            }
        }
        #pragma unroll
        for (int ftr = 0; ftr < 4; ftr++) {
            float2* orow = (float2*)(sm_x2T + (4 * a + ftr) * HT + 16 * h);
            #pragma unroll
            for (int j = 0; j < 8; j++) {
                float lo, hi; upk2(acc[ftr][j], lo, hi);
                orow[j] = make_float2(gelu_f(lo), gelu_f(hi));
            }
        }
    }
    __syncthreads();

    // ---- Phase 4: h2[k][d] = gelu(x2 @ w2^T + b2) + partial pools ----
    // Thread: 4 CONSECUTIVE features {4l..4l+3} (l = lane), token quarter = wid.
    {
        const int l = lane;
        float4 bb = ((const float4*)b2)[l];
        u64 acc[4][4];
        #pragma unroll
        for (int j = 0; j < 4; j++) {
            acc[0][j] = pk2(bb.x, bb.x);
            acc[1][j] = pk2(bb.y, bb.y);
            acc[2][j] = pk2(bb.z, bb.z);
            acc[3][j] = pk2(bb.w, bb.w);
        }
        #pragma unroll 8
        for (int f = 0; f < 256; f++) {
            float4 w = ((const float4*)(g_w2T + (f << 7)))[l];   // feats 4l..4l+3
            u64 wp0 = pk2(w.x, w.x);
            u64 wp1 = pk2(w.y, w.y);
            u64 wp2 = pk2(w.z, w.z);
            u64 wp3 = pk2(w.w, w.w);
            const ulonglong2* xr = (const ulonglong2*)(sm_x2T + f * HT + 8 * wid);
            #pragma unroll
            for (int i = 0; i < 2; i++) {
                ulonglong2 xp = xr[i];   // tokens 8wid+4i .. +3
                acc[0][2*i  ] = fma2(xp.x, wp0, acc[0][2*i  ]);
                acc[0][2*i+1] = fma2(xp.y, wp0, acc[0][2*i+1]);
                acc[1][2*i  ] = fma2(xp.x, wp1, acc[1][2*i  ]);
                acc[1][2*i+1] = fma2(xp.y, wp1, acc[1][2*i+1]);
                acc[2][2*i  ] = fma2(xp.x, wp2, acc[2][2*i  ]);
                acc[2][2*i+1] = fma2(xp.y, wp2, acc[2][2*i+1]);
                acc[3][2*i  ] = fma2(xp.x, wp3, acc[3][2*i  ]);
                acc[3][2*i+1] = fma2(xp.y, wp3, acc[3][2*i+1]);
            }
        }
        // gelu + partial pools over this thread's 8 tokens, per feature
        float* sm_ps = sm_hT;          // [4][128] partial sums
        float* sm_pm = sm_hT + 512;    // [4][128] partial maxes
        #pragma unroll
        for (int ftr = 0; ftr < 4; ftr++) {
            float ps = 0.0f, pm = -INFINITY;
            #pragma unroll
            for (int j = 0; j < 4; j++) {
                float lo, hi; upk2(acc[ftr][j], lo, hi);
                float g0 = gelu_f(lo), g1 = gelu_f(hi);
                ps += g0 + g1;
                pm = fmaxf(pm, fmaxf(g0, g1));
            }
            sm_ps[wid * 128 + 4 * l + ftr] = ps;
            sm_pm[wid * 128 + 4 * l + ftr] = pm;
        }
    }
    __syncthreads();

    // ---- Phase 4b: reduce partials, write pooled to global ----
    {
        float* sm_ps = sm_hT;
        float* sm_pm = sm_hT + 512;
        float s  = sm_ps[t] + sm_ps[128 + t] + sm_ps[256 + t] + sm_ps[384 + t];
        float mx = fmaxf(fmaxf(sm_pm[t], sm_pm[128 + t]), fmaxf(sm_pm[256 + t], sm_pm[384 + t]));
        g_pooled[(size_t)q * 256 + t]       = s * (1.0f / 32.0f);
        g_pooled[(size_t)q * 256 + 128 + t] = mx;
    }
}

// ================= Head kernel: LN(256) + Lin(256,256)+gelu + Lin(256,1) ==========
// One CTA = 32 queries, 256 threads (thread = output feature for the GEMM).
#define K2P 36
__global__ void __launch_bounds__(256)
ff_head_kernel(const float* __restrict__ hln_g, const float* __restrict__ hln_b,
               const float* __restrict__ hb1, const float* __restrict__ hw2,
               const float* __restrict__ hb2, int Q, float* __restrict__ out)
{
    __shared__ float s_pnT[256 * K2P];   // [k][q'] normalized pooled, transposed
    __shared__ float s_hg[256];
    __shared__ float s_hb[256];

    const int t    = threadIdx.x;
    const int lane = t & 31;
    const int w8   = t >> 5;          // warp 0..7
    const int qb   = blockIdx.x * 32;

    s_hg[t] = hln_g[t];
    s_hb[t] = hln_b[t];
    __syncthreads();

    // ---- LN per query (warp per query, 4 queries per warp) ----
    #pragma unroll
    for (int it = 0; it < 4; it++) {
        int qq = w8 * 4 + it;         // 0..31
        int q  = qb + qq;
        if (q < Q) {
            const float* row = g_pooled + (size_t)q * 256;
            float x[8];
            float s = 0.0f, s2 = 0.0f;
            #pragma unroll
            for (int j = 0; j < 8; j++) {
                x[j] = row[lane + 32 * j];
                s += x[j]; s2 += x[j] * x[j];
            }
            #pragma unroll
            for (int o = 16; o; o >>= 1) {
                s  += __shfl_xor_sync(0xffffffffu, s,  o);
                s2 += __shfl_xor_sync(0xffffffffu, s2, o);
            }
            float m   = s * (1.0f / 256.0f);
            float inv = rsqrtf(s2 * (1.0f / 256.0f) - m * m + 1e-5f);
            #pragma unroll
            for (int j = 0; j < 8; j++) {
                int k = lane + 32 * j;
                s_pnT[k * K2P + qq] = (x[j] - m) * inv * s_hg[k] + s_hb[k];
            }
        }
    }
    __syncthreads();

    // ---- GEMM: p[qq][f=t] = gelu( sum_k pn[qq][k] * hw1T[k][t] + hb1[t] ) ----
    u64 acc[16];
    #pragma unroll
    for (int j = 0; j < 16; j++) acc[j] = 0ull;
    #pragma unroll 2
    for (int k = 0; k < 256; k++) {
        float w = g_hw1T[(k << 8) + t];      // coalesced
        u64 wp = pk2(w, w);
        const ulonglong2* xr = (const ulonglong2*)(s_pnT + k * K2P);
        #pragma unroll
        for (int i = 0; i < 8; i++) {
            ulonglong2 xp = xr[i];           // queries 4i..4i+3 (broadcast)
            acc[2*i  ] = fma2(xp.x, wp, acc[2*i  ]);
            acc[2*i+1] = fma2(xp.y, wp, acc[2*i+1]);
        }
    }
    float hb = hb1[t];
    float ws = hw2[t];
    float v[32];
    #pragma unroll
    for (int j = 0; j < 16; j++) {
        float lo, hi; upk2(acc[j], lo, hi);
        v[2*j]   = gelu_f(lo + hb) * ws;
        v[2*j+1] = gelu_f(hi + hb) * ws;
    }
    __syncthreads();                          // all s_pnT reads done
    // scatter contributions: row f = t, col q'
    #pragma unroll
    for (int j = 0; j < 32; j++) s_pnT[t * K2P + j] = v[j];
    __syncthreads();

    // ---- final reduction over 256 features per query ----
    {
        int qq = t >> 3;          // query 0..31
        int c8 = t & 7;           // chunk 0..7 (32 features each)
        float ps = 0.0f;
        #pragma unroll 8
        for (int j = 0; j < 32; j++)
            ps += s_pnT[(c8 * 32 + j) * K2P + qq];
        ps += __shfl_xor_sync(0xffffffffu, ps, 1);
        ps += __shfl_xor_sync(0xffffffffu, ps, 2);
        ps += __shfl_xor_sync(0xffffffffu, ps, 4);
        if (c8 == 0) {
            int q = qb + qq;
            if (q < Q)
                out[q] = (ps + hb2[0]) * g_sig[q] + g_mu[q];
        }
    }
}

extern "C" void kernel_launch(void* const* d_in, const int* in_sizes, int n_in,
                              void* d_out, int out_size)
{
    const float* xyt_q      = (const float*)d_in[0];
    const float* obs_coords = (const float*)d_in[1];
    const float* obs_vals   = (const float*)d_in[2];
    const int*   nb_idx     = (const int*  )d_in[3];
    const float* log_gammas = (const float*)d_in[4];
    const float* w_in       = (const float*)d_in[5];
    const float* b_in       = (const float*)d_in[6];
    const float* ln1_g      = (const float*)d_in[7];
    const float* ln1_b      = (const float*)d_in[8];
    const float* w1         = (const float*)d_in[9];
    const float* b1         = (const float*)d_in[10];
    const float* w2         = (const float*)d_in[11];
    const float* b2         = (const float*)d_in[12];
    const float* hln_g      = (const float*)d_in[13];
    const float* hln_b      = (const float*)d_in[14];
    const float* hw1        = (const float*)d_in[15];
    const float* hb1        = (const float*)d_in[16];
    const float* hw2        = (const float*)d_in[17];
    const float* hb2        = (const float*)d_in[18];
    float* out = (float*)d_out;

    int Q = in_sizes[0] / 3;   // xyt_q is [Q,3]

    transpose_weights<<<256, 256>>>(w1, w2, hw1);

    cudaFuncSetAttribute(ff_body_kernel,
                         cudaFuncAttributeMaxDynamicSharedMemorySize, SMEM_BYTES);

    ff_body_kernel<<<Q, 128, SMEM_BYTES>>>(
        xyt_q, obs_coords, obs_vals, nb_idx, log_gammas,
        w_in, b_in, ln1_g, ln1_b, b1, b2);

    ff_head_kernel<<<(Q + 31) / 32, 256>>>(hln_g, hln_b, hb1, hw2, hb2, Q, out);
}

// round 12
// speedup vs baseline: 1.8107x; 1.0621x over previous
#include <cuda_runtime.h>
#include <math.h>

typedef unsigned long long u64;

__device__ __forceinline__ u64 pk2(float lo, float hi) {
    u64 r; asm("mov.b64 %0, {%1, %2};" : "=l"(r) : "f"(lo), "f"(hi)); return r;
}
__device__ __forceinline__ void upk2(u64 v, float& lo, float& hi) {
    asm("mov.b64 {%0, %1}, %2;" : "=f"(lo), "=f"(hi) : "l"(v));
}
// packed fp32x2 FMA (Blackwell): d = a*b + c on both 32-bit lanes
__device__ __forceinline__ u64 fma2(u64 a, u64 b, u64 c) {
    u64 d; asm("fma.rn.f32x2 %0, %1, %2, %3;" : "=l"(d) : "l"(a), "l"(b), "l"(c)); return d;
}
__device__ __forceinline__ float gelu_f(float x) {
    return 0.5f * x * (1.0f + erff(x * 0.70710678118654752440f));
}

// ---- Transposed weight scratch (coalesced columns; 16B-aligned for float4) ----
__device__ __align__(16) float g_w1T[128 * 256];   // w1T[d][f]  = w1[f][d]
// w2T rows are PERMUTED to match x2T's permuted feature rows:
//   x2T row r holds feature f(r) = 4*(r&63) + (r>>6)  (phase-3 store pattern)
//   so g_w2T[r][d] = w2[d][f(r)].  Phase 4 contracts over r — order irrelevant.
__device__ __align__(16) float g_w2T[256 * 128];
__device__ __align__(16) float g_hw1T[256 * 256];  // hw1T[c][f] = hw1[f][c]
// ---- Inter-kernel scratch ----
#define MAXQ 32768
__device__ __align__(16) float g_pooled[MAXQ * 256];
__device__ float g_mu[MAXQ];
__device__ float g_sig[MAXQ];

__global__ void __launch_bounds__(256)
transpose_weights(const float* __restrict__ w1, const float* __restrict__ w2,
                  const float* __restrict__ hw1)
{
    int i = blockIdx.x * blockDim.x + threadIdx.x;   // 0 .. 65535
    if (i < 256 * 128) {
        int f = i >> 7, d = i & 127;
        g_w1T[d * 256 + f] = w1[i];      // w1 [256][128]
        // w2 [128][256]: element w2[d2][f2] goes to permuted row r(f2) = (f2>>2) + ((f2&3)<<6)
        int d2 = i >> 8, f2 = i & 255;
        int r = (f2 >> 2) + ((f2 & 3) << 6);
        g_w2T[r * 128 + d2] = w2[i];
    }
    if (i < 256 * 256) {
        int f = i >> 8, c = i & 255;
        g_hw1T[c * 256 + f] = hw1[i];    // hw1 [256][256]
    }
}

#define HT 36  // row stride (floats): 144B, 16B-aligned, conflict-padded

// Dynamic SMEM layout (floats):
//   [0      , 4608 )  hT   [128][36]  (token-MLP hidden; reused as pool partials)
//   [4608   , 13824)  x2T  [256][36]  (expanded hidden, PERMUTED feature rows)
//   [13824  , 13952)  tok  [32][4]
//   [13952  , 14080)  ln1_g
//   [14080  , 14208)  ln1_b
//   [14208  , 14240)  sc
#define SMEM_FLOATS 14240
#define SMEM_BYTES  (SMEM_FLOATS * 4)

__global__ void __launch_bounds__(128, 4)
ff_body_kernel(const float* __restrict__ xyt_q, const float* __restrict__ obs_coords,
               const float* __restrict__ obs_vals, const int* __restrict__ nb_idx,
               const float* __restrict__ log_gammas,
               const float* __restrict__ w_in, const float* __restrict__ b_in,
               const float* __restrict__ ln1_g, const float* __restrict__ ln1_b,
               const float* __restrict__ b1, const float* __restrict__ b2)
{
    extern __shared__ float sm[];
    float* sm_hT   = sm;
    float* sm_x2T  = sm + 4608;
    float* sm_tok  = sm + 13824;
    float* sm_g    = sm + 13952;
    float* sm_b    = sm + 14080;
    float* sm_sc   = sm + 14208;

    const int t    = threadIdx.x;
    const int q    = blockIdx.x;
    const int lane = t & 31;
    const int wid  = t >> 5;

    // ---- Phase 0a: preload LN1 params + query coords/gammas ----
    sm_g[t] = ln1_g[t];
    sm_b[t] = ln1_b[t];
    if (t < 3) {
        sm_sc[4 + t] = xyt_q[q * 3 + t];
        sm_sc[8 + t] = expf(log_gammas[t]);
    }
    __syncthreads();

    // ---- Phase 0b: gather neighbors, mu/sigma, build tokens (warp 0) ----
    if (t < 32) {
        int idx  = nb_idx[q * 32 + t];
        float cx = obs_coords[idx * 3 + 0];
        float cy = obs_coords[idx * 3 + 1];
        float cz = obs_coords[idx * 3 + 2];
        float v  = obs_vals[idx];
        float s = v, s2 = v * v;
        #pragma unroll
        for (int o = 16; o; o >>= 1) {
            s  += __shfl_xor_sync(0xffffffffu, s,  o);
            s2 += __shfl_xor_sync(0xffffffffu, s2, o);
        }
        float mu   = s * (1.0f / 32.0f);
        float varu = fmaxf((s2 - s * mu) * (1.0f / 31.0f), 0.0f);  // unbiased (ddof=1)
        float sig  = fmaxf(sqrtf(varu), 1e-3f);
        if (t == 0) { sm_sc[0] = mu; sm_sc[1] = sig; g_mu[q] = mu; g_sig[q] = sig; }
        float4 tk;
        tk.x = (cx - sm_sc[4]) * sm_sc[8];
        tk.y = (cy - sm_sc[5]) * sm_sc[9];
        tk.z = (cz - sm_sc[6]) * sm_sc[10];
        tk.w = (v - mu) / sig;
        ((float4*)sm_tok)[t] = tk;
    }
    __syncthreads();

    // ---- Phase 1: h[k][d] = gelu(tokens @ w_in^T + b_in); thread = channel d ----
    // Stores as float2 pairs (same row, adjacent cols): halves STS wavefronts.
    {
        float4 wv = ((const float4*)w_in)[t];
        float  bw = b_in[t];
        float* hrow = sm_hT + t * HT;
        #pragma unroll
        for (int k = 0; k < 32; k += 2) {
            float4 tk0 = ((const float4*)sm_tok)[k];
            float4 tk1 = ((const float4*)sm_tok)[k + 1];
            float a0 = fmaf(tk0.w, wv.w, fmaf(tk0.z, wv.z, fmaf(tk0.y, wv.y, fmaf(tk0.x, wv.x, bw))));
            float a1 = fmaf(tk1.w, wv.w, fmaf(tk1.z, wv.z, fmaf(tk1.y, wv.y, fmaf(tk1.x, wv.x, bw))));
            *(float2*)&hrow[k] = make_float2(gelu_f(a0), gelu_f(a1));
        }
    }
    __syncthreads();

    // ---- Phase 2: LayerNorm over D, token PAIRS per pass (float2 col access) ----
    {
        #pragma unroll
        for (int kp = 0; kp < 4; kp++) {
            int k = wid * 8 + kp * 2;
            float2 x0 = *(const float2*)&sm_hT[(lane      ) * HT + k];
            float2 x1 = *(const float2*)&sm_hT[(lane + 32 ) * HT + k];
            float2 x2 = *(const float2*)&sm_hT[(lane + 64 ) * HT + k];
            float2 x3 = *(const float2*)&sm_hT[(lane + 96 ) * HT + k];
            float sA  = x0.x + x1.x + x2.x + x3.x;
            float sB  = x0.y + x1.y + x2.y + x3.y;
            float s2A = x0.x*x0.x + x1.x*x1.x + x2.x*x2.x + x3.x*x3.x;
            float s2B = x0.y*x0.y + x1.y*x1.y + x2.y*x2.y + x3.y*x3.y;
            #pragma unroll
            for (int o = 16; o; o >>= 1) {
                sA  += __shfl_xor_sync(0xffffffffu, sA,  o);
                s2A += __shfl_xor_sync(0xffffffffu, s2A, o);
                sB  += __shfl_xor_sync(0xffffffffu, sB,  o);
                s2B += __shfl_xor_sync(0xffffffffu, s2B, o);
            }
            float mA   = sA * (1.0f / 128.0f);
            float invA = rsqrtf(s2A * (1.0f / 128.0f) - mA * mA + 1e-5f);
            float mB   = sB * (1.0f / 128.0f);
            float invB = rsqrtf(s2B * (1.0f / 128.0f) - mB * mB + 1e-5f);
            float g0 = sm_g[lane      ], c0 = sm_b[lane      ];
            float g1 = sm_g[lane + 32 ], c1 = sm_b[lane + 32 ];
            float g2 = sm_g[lane + 64 ], c2 = sm_b[lane + 64 ];
            float g3 = sm_g[lane + 96 ], c3 = sm_b[lane + 96 ];
            *(float2*)&sm_hT[(lane      ) * HT + k] =
                make_float2((x0.x - mA) * invA * g0 + c0, (x0.y - mB) * invB * g0 + c0);
            *(float2*)&sm_hT[(lane + 32 ) * HT + k] =
                make_float2((x1.x - mA) * invA * g1 + c1, (x1.y - mB) * invB * g1 + c1);
            *(float2*)&sm_hT[(lane + 64 ) * HT + k] =
                make_float2((x2.x - mA) * invA * g2 + c2, (x2.y - mB) * invB * g2 + c2);
            *(float2*)&sm_hT[(lane + 96 ) * HT + k] =
                make_float2((x3.x - mA) * invA * g3 + c3, (x3.y - mB) * invB * g3 + c3);
        }
    }
    __syncthreads();

    // ---- Phase 3: x2[k][f] = gelu(xn @ w1^T + b1) ----
    // Thread: 4 consecutive features {4a..4a+3} (a = t&63), token half h = t>>6.
    // Weight fetch = one LDG.128 per d. Output rows PERMUTED: feature 4a+ftr
    // stored at row a + 64*ftr -> lane-consecutive rows -> 4-way (not 16-way) STS.
    {
        const int a = t & 63;
        const int h = t >> 6;
        float4 bb = ((const float4*)b1)[a];
        u64 acc[4][8];
        #pragma unroll
        for (int j = 0; j < 8; j++) {
            acc[0][j] = pk2(bb.x, bb.x);
            acc[1][j] = pk2(bb.y, bb.y);
            acc[2][j] = pk2(bb.z, bb.z);
            acc[3][j] = pk2(bb.w, bb.w);
        }
        #pragma unroll 4
        for (int d = 0; d < 128; d++) {
            float4 w = ((const float4*)(g_w1T + (d << 8)))[a];   // feats 4a..4a+3
            u64 wp0 = pk2(w.x, w.x);
            u64 wp1 = pk2(w.y, w.y);
            u64 wp2 = pk2(w.z, w.z);
            u64 wp3 = pk2(w.w, w.w);
            const ulonglong2* xr = (const ulonglong2*)(sm_hT + d * HT + 16 * h);
            #pragma unroll
            for (int i = 0; i < 4; i++) {
                ulonglong2 xp = xr[i];   // tokens 16h+4i .. 16h+4i+3
                acc[0][2*i  ] = fma2(xp.x, wp0, acc[0][2*i  ]);
                acc[0][2*i+1] = fma2(xp.y, wp0, acc[0][2*i+1]);
                acc[1][2*i  ] = fma2(xp.x, wp1, acc[1][2*i  ]);
                acc[1][2*i+1] = fma2(xp.y, wp1, acc[1][2*i+1]);
                acc[2][2*i  ] = fma2(xp.x, wp2, acc[2][2*i  ]);
                acc[2][2*i+1] = fma2(xp.y, wp2, acc[2][2*i+1]);
                acc[3][2*i  ] = fma2(xp.x, wp3, acc[3][2*i  ]);
                acc[3][2*i+1] = fma2(xp.y, wp3, acc[3][2*i+1]);
            }
        }
        #pragma unroll
        for (int ftr = 0; ftr < 4; ftr++) {
            // permuted row: feature 4a+ftr -> row a + 64*ftr
            float2* orow = (float2*)(sm_x2T + (a + (ftr << 6)) * HT + 16 * h);
            #pragma unroll
            for (int j = 0; j < 8; j++) {
                float lo, hi; upk2(acc[ftr][j], lo, hi);
                orow[j] = make_float2(gelu_f(lo), gelu_f(hi));
            }
        }
    }
    __syncthreads();

    // ---- Phase 4: h2[k][d] = gelu(x2 @ w2^T + b2) + partial pools ----
    // Contracts over permuted rows r: x2T row r matches g_w2T row r by construction.
    // Thread: 4 consecutive output channels {4l..4l+3} (l = lane), token quarter = wid.
    {
        const int l = lane;
        float4 bb = ((const float4*)b2)[l];
        u64 acc[4][4];
        #pragma unroll
        for (int j = 0; j < 4; j++) {
            acc[0][j] = pk2(bb.x, bb.x);
            acc[1][j] = pk2(bb.y, bb.y);
            acc[2][j] = pk2(bb.z, bb.z);
            acc[3][j] = pk2(bb.w, bb.w);
        }
        #pragma unroll 8
        for (int f = 0; f < 256; f++) {
            float4 w = ((const float4*)(g_w2T + (f << 7)))[l];   // channels 4l..4l+3
            u64 wp0 = pk2(w.x, w.x);
            u64 wp1 = pk2(w.y, w.y);
            u64 wp2 = pk2(w.z, w.z);
            u64 wp3 = pk2(w.w, w.w);
            const ulonglong2* xr = (const ulonglong2*)(sm_x2T + f * HT + 8 * wid);
            #pragma unroll
            for (int i = 0; i < 2; i++) {
                ulonglong2 xp = xr[i];   // tokens 8wid+4i .. +3
                acc[0][2*i  ] = fma2(xp.x, wp0, acc[0][2*i  ]);
                acc[0][2*i+1] = fma2(xp.y, wp0, acc[0][2*i+1]);
                acc[1][2*i  ] = fma2(xp.x, wp1, acc[1][2*i  ]);
                acc[1][2*i+1] = fma2(xp.y, wp1, acc[1][2*i+1]);
                acc[2][2*i  ] = fma2(xp.x, wp2, acc[2][2*i  ]);
                acc[2][2*i+1] = fma2(xp.y, wp2, acc[2][2*i+1]);
                acc[3][2*i  ] = fma2(xp.x, wp3, acc[3][2*i  ]);
                acc[3][2*i+1] = fma2(xp.y, wp3, acc[3][2*i+1]);
            }
        }
        // gelu + partial pools over this thread's 8 tokens, per channel
        float* sm_ps = sm_hT;          // [4][128] partial sums
        float* sm_pm = sm_hT + 512;    // [4][128] partial maxes
        #pragma unroll
        for (int ftr = 0; ftr < 4; ftr++) {
            float ps = 0.0f, pm = -INFINITY;
            #pragma unroll
            for (int j = 0; j < 4; j++) {
                float lo, hi; upk2(acc[ftr][j], lo, hi);
                float g0 = gelu_f(lo), g1 = gelu_f(hi);
                ps += g0 + g1;
                pm = fmaxf(pm, fmaxf(g0, g1));
            }
            sm_ps[wid * 128 + 4 * l + ftr] = ps;
            sm_pm[wid * 128 + 4 * l + ftr] = pm;
        }
    }
    __syncthreads();

    // ---- Phase 4b: reduce partials, write pooled to global ----
    {
        float* sm_ps = sm_hT;
        float* sm_pm = sm_hT + 512;
        float s  = sm_ps[t] + sm_ps[128 + t] + sm_ps[256 + t] + sm_ps[384 + t];
        float mx = fmaxf(fmaxf(sm_pm[t], sm_pm[128 + t]), fmaxf(sm_pm[256 + t], sm_pm[384 + t]));
        g_pooled[(size_t)q * 256 + t]       = s * (1.0f / 32.0f);
        g_pooled[(size_t)q * 256 + 128 + t] = mx;
    }
}

// ================= Head kernel: LN(256) + Lin(256,256)+gelu + Lin(256,1) ==========
// One CTA = 32 queries, 256 threads (thread = output feature for the GEMM).
#define K2P 36
__global__ void __launch_bounds__(256)
ff_head_kernel(const float* __restrict__ hln_g, const float* __restrict__ hln_b,
               const float* __restrict__ hb1, const float* __restrict__ hw2,
               const float* __restrict__ hb2, int Q, float* __restrict__ out)
{
    __shared__ float s_pnT[256 * K2P];   // [k][q'] normalized pooled, transposed
    __shared__ float s_hg[256];
    __shared__ float s_hb[256];

    const int t    = threadIdx.x;
    const int lane = t & 31;
    const int w8   = t >> 5;          // warp 0..7
    const int qb   = blockIdx.x * 32;

    s_hg[t] = hln_g[t];
    s_hb[t] = hln_b[t];
    __syncthreads();

    // ---- LN per query (warp per query, 4 queries per warp) ----
    #pragma unroll
    for (int it = 0; it < 4; it++) {
        int qq = w8 * 4 + it;         // 0..31
        int q  = qb + qq;
        if (q < Q) {
            const float* row = g_pooled + (size_t)q * 256;
            float x[8];
            float s = 0.0f, s2 = 0.0f;
            #pragma unroll
            for (int j = 0; j < 8; j++) {
                x[j] = row[lane + 32 * j];
                s += x[j]; s2 += x[j] * x[j];
            }
            #pragma unroll
            for (int o = 16; o; o >>= 1) {
                s  += __shfl_xor_sync(0xffffffffu, s,  o);
                s2 += __shfl_xor_sync(0xffffffffu, s2, o);
            }
            float m   = s * (1.0f / 256.0f);
            float inv = rsqrtf(s2 * (1.0f / 256.0f) - m * m + 1e-5f);
            #pragma unroll
            for (int j = 0; j < 8; j++) {
                int k = lane + 32 * j;
                s_pnT[k * K2P + qq] = (x[j] - m) * inv * s_hg[k] + s_hb[k];
            }
        }
    }
    __syncthreads();

    // ---- GEMM: p[qq][f=t] = gelu( sum_k pn[qq][k] * hw1T[k][t] + hb1[t] ) ----
    u64 acc[16];
    #pragma unroll
    for (int j = 0; j < 16; j++) acc[j] = 0ull;
    #pragma unroll 2
    for (int k = 0; k < 256; k++) {
        float w = g_hw1T[(k << 8) + t];      // coalesced
        u64 wp = pk2(w, w);
        const ulonglong2* xr = (const ulonglong2*)(s_pnT + k * K2P);
        #pragma unroll
        for (int i = 0; i < 8; i++) {
            ulonglong2 xp = xr[i];           // queries 4i..4i+3 (broadcast)
            acc[2*i  ] = fma2(xp.x, wp, acc[2*i  ]);
            acc[2*i+1] = fma2(xp.y, wp, acc[2*i+1]);
        }
    }
    float hb = hb1[t];
    float ws = hw2[t];
    float v[32];
    #pragma unroll
    for (int j = 0; j < 16; j++) {
        float lo, hi; upk2(acc[j], lo, hi);
        v[2*j]   = gelu_f(lo + hb) * ws;
        v[2*j+1] = gelu_f(hi + hb) * ws;
    }
    __syncthreads();                          // all s_pnT reads done
    // scatter contributions: row f = t, col q'
    #pragma unroll
    for (int j = 0; j < 32; j++) s_pnT[t * K2P + j] = v[j];
    __syncthreads();

    // ---- final reduction over 256 features per query ----
    {
        int qq = t >> 3;          // query 0..31
        int c8 = t & 7;           // chunk 0..7 (32 features each)
        float ps = 0.0f;
        #pragma unroll 8
        for (int j = 0; j < 32; j++)
            ps += s_pnT[(c8 * 32 + j) * K2P + qq];
        ps += __shfl_xor_sync(0xffffffffu, ps, 1);
        ps += __shfl_xor_sync(0xffffffffu, ps, 2);
        ps += __shfl_xor_sync(0xffffffffu, ps, 4);
        if (c8 == 0) {
            int q = qb + qq;
            if (q < Q)
                out[q] = (ps + hb2[0]) * g_sig[q] + g_mu[q];
        }
    }
}

extern "C" void kernel_launch(void* const* d_in, const int* in_sizes, int n_in,
                              void* d_out, int out_size)
{
    const float* xyt_q      = (const float*)d_in[0];
    const float* obs_coords = (const float*)d_in[1];
    const float* obs_vals   = (const float*)d_in[2];
    const int*   nb_idx     = (const int*  )d_in[3];
    const float* log_gammas = (const float*)d_in[4];
    const float* w_in       = (const float*)d_in[5];
    const float* b_in       = (const float*)d_in[6];
    const float* ln1_g      = (const float*)d_in[7];
    const float* ln1_b      = (const float*)d_in[8];
    const float* w1         = (const float*)d_in[9];
    const float* b1         = (const float*)d_in[10];
    const float* w2         = (const float*)d_in[11];
    const float* b2         = (const float*)d_in[12];
    const float* hln_g      = (const float*)d_in[13];
    const float* hln_b      = (const float*)d_in[14];
    const float* hw1        = (const float*)d_in[15];
    const float* hb1        = (const float*)d_in[16];
    const float* hw2        = (const float*)d_in[17];
    const float* hb2        = (const float*)d_in[18];
    float* out = (float*)d_out;

    int Q = in_sizes[0] / 3;   // xyt_q is [Q,3]

    transpose_weights<<<256, 256>>>(w1, w2, hw1);

    cudaFuncSetAttribute(ff_body_kernel,
                         cudaFuncAttributeMaxDynamicSharedMemorySize, SMEM_BYTES);

    ff_body_kernel<<<Q, 128, SMEM_BYTES>>>(
        xyt_q, obs_coords, obs_vals, nb_idx, log_gammas,
        w_in, b_in, ln1_g, ln1_b, b1, b2);

    ff_head_kernel<<<(Q + 31) / 32, 256>>>(hln_g, hln_b, hb1, hw2, hb2, Q, out);
}

// round 17
// speedup vs baseline: 2.1260x; 1.1741x over previous
#include <cuda_runtime.h>
#include <cuda_bf16.h>
#include <math.h>
#include <stdint.h>

typedef unsigned long long u64;

__device__ __forceinline__ float gelu_f(float x) {
    return 0.5f * x * (1.0f + erff(x * 0.70710678118654752440f));
}
__device__ __forceinline__ uint32_t s2u(const void* p) {
    uint32_t a;
    asm("{ .reg .u64 t; cvta.to.shared.u64 t, %1; cvt.u32.u64 %0, t; }" : "=r"(a) : "l"(p));
    return a;
}
__device__ __forceinline__ uint32_t pkbf(float a, float b) {
    __nv_bfloat162 t; t.x = __float2bfloat16_rn(a); t.y = __float2bfloat16_rn(b);
    return *reinterpret_cast<uint32_t*>(&t);
}

#define LDSM4(r0,r1,r2,r3, addr) \
    asm volatile("ldmatrix.sync.aligned.m8n8.x4.shared.b16 {%0,%1,%2,%3}, [%4];" \
                 : "=r"(r0), "=r"(r1), "=r"(r2), "=r"(r3) : "r"(addr))
#define LDSM2(r0,r1, addr) \
    asm volatile("ldmatrix.sync.aligned.m8n8.x2.shared.b16 {%0,%1}, [%2];" \
                 : "=r"(r0), "=r"(r1) : "r"(addr))
#define MMA16816(d, a0,a1,a2,a3, b0,b1) \
    asm volatile("mma.sync.aligned.m16n8k16.row.col.f32.bf16.bf16.f32 " \
                 "{%0,%1,%2,%3}, {%4,%5,%6,%7}, {%8,%9}, {%0,%1,%2,%3};" \
                 : "+f"((d)[0]), "+f"((d)[1]), "+f"((d)[2]), "+f"((d)[3]) \
                 : "r"(a0), "r"(a1), "r"(a2), "r"(a3), "r"(b0), "r"(b1))

// ---- bf16 hi/lo weight images (plain row-major) + scratch ----
__device__ __align__(16) __nv_bfloat16 g_w1hi[256 * 128], g_w1lo[256 * 128];  // [f][d]
__device__ __align__(16) __nv_bfloat16 g_w2hi[128 * 256], g_w2lo[128 * 256];  // [d][f]
__device__ __align__(16) float g_hw1T[256 * 256];
#define MAXQ 32768
__device__ __align__(16) float g_pooled[MAXQ * 256];
__device__ float g_mu[MAXQ], g_sig[MAXQ];

__global__ void __launch_bounds__(256)
convert_weights(const float* __restrict__ w1, const float* __restrict__ w2,
                const float* __restrict__ hw1)
{
    int i = blockIdx.x * blockDim.x + threadIdx.x;   // 0..65535
    if (i < 256 * 128) {
        float v = w1[i];
        __nv_bfloat16 h = __float2bfloat16_rn(v);
        g_w1hi[i] = h;
        g_w1lo[i] = __float2bfloat16_rn(v - __bfloat162float(h));
        float v2 = w2[i];
        __nv_bfloat16 h2 = __float2bfloat16_rn(v2);
        g_w2hi[i] = h2;
        g_w2lo[i] = __float2bfloat16_rn(v2 - __bfloat162float(h2));
    }
    if (i < 256 * 256) {
        int f = i >> 8, c = i & 255;
        g_hw1T[c * 256 + f] = hw1[i];
    }
}

// SMEM bytes: A1H 0 | A1L 34816 | A2H 69632 | A2L 104448 | BST 139264 (34816)
// misc floats @43520: tok4[128*4] | pS[256]@44032 | pS2[256]@44288 | b1[256]@44544
//                     b2[128]@44800 | lng[128]@44928 | lnb[128]@45056 | end 45184 floats
// h2 overlay: f32 [128][137] @0 (70144B <= A1H+A1L)
#define A1H 0
#define A1L 34816
#define A2H 69632
#define A2L 104448
#define BST 139264
#define RS  272            // bf16 tile row stride bytes (17 x 16B, conflict-free LDSM)
#define DSMEM_BYTES (45184 * 4)

__device__ __forceinline__ void gemm_pass(uint32_t Aaddr, uint32_t Baddr, float (&acc)[16][4]) {
    #pragma unroll 1
    for (int kk = 0; kk < 8; kk++) {
        uint32_t a0, a1, a2, a3;
        LDSM4(a0, a1, a2, a3, Aaddr + kk * 32);
        #pragma unroll
        for (int j = 0; j < 16; j++) {
            uint32_t b0, b1;
            LDSM2(b0, b1, Baddr + kk * 32 + j * (8 * RS));
            MMA16816(acc[j], a0, a1, a2, a3, b0, b1);
        }
    }
}

__device__ __forceinline__ void stage_B(const uint4* __restrict__ src, int row_stride_u4,
                                        char* smB, int t) {
    #pragma unroll 1
    for (int i = t; i < 2048; i += 256) {
        int row = i >> 4, seg = i & 15;
        *(uint4*)(smB + row * RS + (seg << 4)) = src[row * row_stride_u4 + seg];
    }
}

__global__ void __launch_bounds__(256, 1)
ff_mma_kernel(const float* __restrict__ xyt_q, const float* __restrict__ obs_coords,
              const float* __restrict__ obs_vals, const int* __restrict__ nb_idx,
              const float* __restrict__ log_gammas,
              const float* __restrict__ w_in, const float* __restrict__ b_in,
              const float* __restrict__ ln1_g, const float* __restrict__ ln1_b,
              const float* __restrict__ b1, const float* __restrict__ b2, int Q)
{
    extern __shared__ float sm[];
    char* smc = (char*)sm;
    const uint32_t sb = s2u(sm);
    float4* sm_tok4 = (float4*)(sm + 43520);
    float*  sm_pS   = sm + 44032;
    float*  sm_pS2  = sm + 44288;
    float*  sm_b1   = sm + 44544;
    float*  sm_b2   = sm + 44800;
    float*  sm_lng  = sm + 44928;
    float*  sm_lnb  = sm + 45056;

    const int t = threadIdx.x, wid = t >> 5, lane = t & 31;
    const int qb = blockIdx.x * 4;
    const int tok = t & 127, half = t >> 7;

    if (t < 256) sm_b1[t] = b1[t];
    if (t < 128) { sm_b2[t] = b2[t]; sm_lng[t] = ln1_g[t]; sm_lnb[t] = ln1_b[t]; }

    // ---- token build (warps 0-3: warp = query, lane = neighbor) ----
    if (t < 128) {
        int q = qb + wid;
        bool ok = (q < Q);
        int idx = ok ? nb_idx[q * 32 + lane] : 0;
        float cx = obs_coords[idx * 3 + 0], cy = obs_coords[idx * 3 + 1], cz = obs_coords[idx * 3 + 2];
        float v  = obs_vals[idx];
        float s = v, s2 = v * v;
        #pragma unroll
        for (int o = 16; o; o >>= 1) {
            s  += __shfl_xor_sync(0xffffffffu, s,  o);
            s2 += __shfl_xor_sync(0xffffffffu, s2, o);
        }
        float mu  = s * (1.0f / 32.0f);
        float var = fmaxf((s2 - s * mu) * (1.0f / 31.0f), 0.0f);
        float sig = fmaxf(sqrtf(var), 1e-3f);
        if (lane == 0 && ok) { g_mu[q] = mu; g_sig[q] = sig; }
        float qx = ok ? xyt_q[q * 3 + 0] : 0.f, qy = ok ? xyt_q[q * 3 + 1] : 0.f, qz = ok ? xyt_q[q * 3 + 2] : 0.f;
        float4 tk;
        tk.x = (cx - qx) * expf(log_gammas[0]);
        tk.y = (cy - qy) * expf(log_gammas[1]);
        tk.z = (cz - qz) * expf(log_gammas[2]);
        tk.w = (v - mu) / sig;
        sm_tok4[wid * 32 + lane] = tk;
    }
    __syncthreads();

    // ---- phase1: h = gelu(tok @ w_in^T + b_in); thread = (token, 64-channel half) ----
    float4 tk = sm_tok4[tok];
    float h[64];
    {
        float s = 0.f, s2 = 0.f;
        #pragma unroll
        for (int j = 0; j < 64; j++) {
            int d = (half << 6) + j;
            float4 wv = ((const float4*)w_in)[d];
            float a = fmaf(tk.w, wv.w, fmaf(tk.z, wv.z, fmaf(tk.y, wv.y, fmaf(tk.x, wv.x, b_in[d]))));
            float g = gelu_f(a);
            h[j] = g; s += g; s2 += g * g;
        }
        sm_pS [(half << 7) + tok] = s;
        sm_pS2[(half << 7) + tok] = s2;
    }
    __syncthreads();

    // ---- LN + bf16 hi/lo split -> A1 SMEM (row = token, K-major, 272B stride) ----
    {
        float S  = sm_pS[tok]  + sm_pS[128 + tok];
        float S2 = sm_pS2[tok] + sm_pS2[128 + tok];
        float m   = S * (1.0f / 128.0f);
        float inv = rsqrtf(S2 * (1.0f / 128.0f) - m * m + 1e-5f);
        #pragma unroll
        for (int jp = 0; jp < 32; jp++) {
            int d0 = (half << 6) + 2 * jp;
            float x0 = (h[2*jp]   - m) * inv * sm_lng[d0]   + sm_lnb[d0];
            float x1 = (h[2*jp+1] - m) * inv * sm_lng[d0+1] + sm_lnb[d0+1];
            __nv_bfloat16 h0 = __float2bfloat16_rn(x0), h1 = __float2bfloat16_rn(x1);
            int boff = tok * RS + d0 * 2;
            *(uint32_t*)(smc + A1H + boff) = pkbf(x0, x1);
            *(uint32_t*)(smc + A1L + boff) = pkbf(x0 - __bfloat162float(h0), x1 - __bfloat162float(h1));
        }
    }

    // per-thread LDSM offsets
    const uint32_t aoff = (uint32_t)((16 * wid + (lane & 15)) * RS + ((lane >> 4) << 4));
    const uint32_t boff = (uint32_t)((lane & 7) * RS + (((lane >> 3) & 1) << 4));
    const uint32_t Bb = sb + BST + boff;

    float acc2[16][4];
    #pragma unroll
    for (int j = 0; j < 16; j++)
        #pragma unroll
        for (int c = 0; c < 4; c++) acc2[j][c] = 0.f;

    for (int nh = 0; nh < 2; nh++) {
        // ---- GEMM1 N-half nh: acc1 = A1 @ w1[nh*128..]^T (3-pass split) ----
        float acc1[16][4];
        #pragma unroll
        for (int j = 0; j < 16; j++)
            #pragma unroll
            for (int c = 0; c < 4; c++) acc1[j][c] = 0.f;

        __syncthreads();
        stage_B((const uint4*)g_w1hi + nh * 128 * 16, 16, smc + BST, t);
        __syncthreads();
        gemm_pass(sb + A1H + aoff, Bb, acc1);
        gemm_pass(sb + A1L + aoff, Bb, acc1);
        __syncthreads();
        stage_B((const uint4*)g_w1lo + nh * 128 * 16, 16, smc + BST, t);
        __syncthreads();
        gemm_pass(sb + A1H + aoff, Bb, acc1);

        // ---- epilogue1: gelu(+b1), split, store A2 (rows warp-private) ----
        {
            int r0 = 16 * wid + (lane >> 2);
            #pragma unroll
            for (int j = 0; j < 16; j++) {
                int colL = (j << 3) + 2 * (lane & 3);
                float bb0 = sm_b1[nh * 128 + colL], bb1 = sm_b1[nh * 128 + colL + 1];
                float v00 = gelu_f(acc1[j][0] + bb0), v01 = gelu_f(acc1[j][1] + bb1);
                float v10 = gelu_f(acc1[j][2] + bb0), v11 = gelu_f(acc1[j][3] + bb1);
                __nv_bfloat16 a00 = __float2bfloat16_rn(v00), a01 = __float2bfloat16_rn(v01);
                __nv_bfloat16 a10 = __float2bfloat16_rn(v10), a11 = __float2bfloat16_rn(v11);
                int o0 = r0 * RS + colL * 2, o1 = (r0 + 8) * RS + colL * 2;
                *(uint32_t*)(smc + A2H + o0) = pkbf(v00, v01);
                *(uint32_t*)(smc + A2H + o1) = pkbf(v10, v11);
                *(uint32_t*)(smc + A2L + o0) = pkbf(v00 - __bfloat162float(a00), v01 - __bfloat162float(a01));
                *(uint32_t*)(smc + A2L + o1) = pkbf(v10 - __bfloat162float(a10), v11 - __bfloat162float(a11));
            }
        }
        __syncwarp();

        // ---- GEMM2 K-half nh: acc2 += A2 @ w2[:, nh*128..]^T (3-pass split) ----
        __syncthreads();
        stage_B((const uint4*)g_w2hi + nh * 16, 32, smc + BST, t);
        __syncthreads();
        gemm_pass(sb + A2H + aoff, Bb, acc2);
        gemm_pass(sb + A2L + aoff, Bb, acc2);
        __syncthreads();
        stage_B((const uint4*)g_w2lo + nh * 16, 32, smc + BST, t);
        __syncthreads();
        gemm_pass(sb + A2H + aoff, Bb, acc2);
    }

    // ---- epilogue2: gelu(+b2) -> h2 f32 [128][137] (overlay on A1) ----
    __syncthreads();                       // Bst reads done; A1 region now dead
    {
        float* h2 = sm;                    // stride 137 floats
        int r0 = 16 * wid + (lane >> 2);
        #pragma unroll
        for (int j = 0; j < 16; j++) {
            int ch = (j << 3) + 2 * (lane & 3);
            float bb0 = sm_b2[ch], bb1 = sm_b2[ch + 1];
            h2[r0 * 137 + ch]           = gelu_f(acc2[j][0] + bb0);
            h2[r0 * 137 + ch + 1]       = gelu_f(acc2[j][1] + bb1);
            h2[(r0 + 8) * 137 + ch]     = gelu_f(acc2[j][2] + bb0);
            h2[(r0 + 8) * 137 + ch + 1] = gelu_f(acc2[j][3] + bb1);
        }
    }
    __syncthreads();

    // ---- pooling: thread = (channel t&127, queries t>>7 and +2) ----
    {
        const float* h2 = sm;
        int ch = t & 127;
        #pragma unroll
        for (int qi = (t >> 7); qi < 4; qi += 2) {
            float s = 0.f, mx = -INFINITY;
            #pragma unroll 8
            for (int r = 0; r < 32; r++) {
                float v = h2[(qi * 32 + r) * 137 + ch];
                s += v; mx = fmaxf(mx, v);
            }
            int q = qb + qi;
            if (q < Q) {
                g_pooled[(size_t)q * 256 + ch]       = s * (1.0f / 32.0f);
                g_pooled[(size_t)q * 256 + 128 + ch] = mx;
            }
        }
    }
}

// ============== head kernel (verified R12 version) ==============
__device__ __forceinline__ u64 pk2(float lo, float hi) {
    u64 r; asm("mov.b64 %0, {%1, %2};" : "=l"(r) : "f"(lo), "f"(hi)); return r;
}
__device__ __forceinline__ void upk2(u64 v, float& lo, float& hi) {
    asm("mov.b64 {%0, %1}, %2;" : "=f"(lo), "=f"(hi) : "l"(v));
}
__device__ __forceinline__ u64 fma2(u64 a, u64 b, u64 c) {
    u64 d; asm("fma.rn.f32x2 %0, %1, %2, %3;" : "=l"(d) : "l"(a), "l"(b), "l"(c)); return d;
}
#define K2P 36
__global__ void __launch_bounds__(256)
ff_head_kernel(const float* __restrict__ hln_g, const float* __restrict__ hln_b,
               const float* __restrict__ hb1, const float* __restrict__ hw2,
               const float* __restrict__ hb2, int Q, float* __restrict__ out)
{
    __shared__ float s_pnT[256 * K2P];
    __shared__ float s_hg[256], s_hb[256];
    const int t = threadIdx.x, lane = t & 31, w8 = t >> 5, qb = blockIdx.x * 32;
    s_hg[t] = hln_g[t];
    s_hb[t] = hln_b[t];
    __syncthreads();
    #pragma unroll
    for (int it = 0; it < 4; it++) {
        int qq = w8 * 4 + it, q = qb + qq;
        if (q < Q) {
            const float* row = g_pooled + (size_t)q * 256;
            float x[8], s = 0.f, s2 = 0.f;
            #pragma unroll
            for (int j = 0; j < 8; j++) { x[j] = row[lane + 32 * j]; s += x[j]; s2 += x[j] * x[j]; }
            #pragma unroll
            for (int o = 16; o; o >>= 1) {
                s  += __shfl_xor_sync(0xffffffffu, s,  o);
                s2 += __shfl_xor_sync(0xffffffffu, s2, o);
            }
            float m = s * (1.0f / 256.0f);
            float inv = rsqrtf(s2 * (1.0f / 256.0f) - m * m + 1e-5f);
            #pragma unroll
            for (int j = 0; j < 8; j++) {
                int k = lane + 32 * j;
                s_pnT[k * K2P + qq] = (x[j] - m) * inv * s_hg[k] + s_hb[k];
            }
        }
    }
    __syncthreads();
    u64 acc[16];
    #pragma unroll
    for (int j = 0; j < 16; j++) acc[j] = 0ull;
    #pragma unroll 2
    for (int k = 0; k < 256; k++) {
        float w = g_hw1T[(k << 8) + t];
        u64 wp = pk2(w, w);
        const ulonglong2* xr = (const ulonglong2*)(s_pnT + k * K2P);
        #pragma unroll
        for (int i = 0; i < 8; i++) {
            ulonglong2 xp = xr[i];
            acc[2*i  ] = fma2(xp.x, wp, acc[2*i  ]);
            acc[2*i+1] = fma2(xp.y, wp, acc[2*i+1]);
        }
    }
    float hb = hb1[t], ws = hw2[t];
    float v[32];
    #pragma unroll
    for (int j = 0; j < 16; j++) {
        float lo, hi; upk2(acc[j], lo, hi);
        v[2*j]   = gelu_f(lo + hb) * ws;
        v[2*j+1] = gelu_f(hi + hb) * ws;
    }
    __syncthreads();
    #pragma unroll
    for (int j = 0; j < 32; j++) s_pnT[t * K2P + j] = v[j];
    __syncthreads();
    {
        int qq = t >> 3, c8 = t & 7;
        float ps = 0.0f;
        #pragma unroll 8
        for (int j = 0; j < 32; j++) ps += s_pnT[(c8 * 32 + j) * K2P + qq];
        ps += __shfl_xor_sync(0xffffffffu, ps, 1);
        ps += __shfl_xor_sync(0xffffffffu, ps, 2);
        ps += __shfl_xor_sync(0xffffffffu, ps, 4);
        if (c8 == 0) {
            int q = qb + qq;
            if (q < Q) out[q] = (ps + hb2[0]) * g_sig[q] + g_mu[q];
        }
    }
}

extern "C" void kernel_launch(void* const* d_in, const int* in_sizes, int n_in,
                              void* d_out, int out_size)
{
    const float* xyt_q      = (const float*)d_in[0];
    const float* obs_coords = (const float*)d_in[1];
    const float* obs_vals   = (const float*)d_in[2];
    const int*   nb_idx     = (const int*  )d_in[3];
    const float* log_gammas = (const float*)d_in[4];
    const float* w_in = (const float*)d_in[5];
    const float* b_in = (const float*)d_in[6];
    const float* ln1_g = (const float*)d_in[7];
    const float* ln1_b = (const float*)d_in[8];
    const float* w1 = (const float*)d_in[9];
    const float* b1 = (const float*)d_in[10];
    const float* w2 = (const float*)d_in[11];
    const float* b2 = (const float*)d_in[12];
    const float* hln_g = (const float*)d_in[13];
    const float* hln_b = (const float*)d_in[14];
    const float* hw1 = (const float*)d_in[15];
    const float* hb1 = (const float*)d_in[16];
    const float* hw2 = (const float*)d_in[17];
    const float* hb2 = (const float*)d_in[18];
    float* out = (float*)d_out;
    int Q = in_sizes[0] / 3;

    convert_weights<<<256, 256>>>(w1, w2, hw1);

    cudaFuncSetAttribute(ff_mma_kernel, cudaFuncAttributeMaxDynamicSharedMemorySize, DSMEM_BYTES);
    ff_mma_kernel<<<(Q + 3) / 4, 256, DSMEM_BYTES>>>(
        xyt_q, obs_coords, obs_vals, nb_idx, log_gammas,
        w_in, b_in, ln1_g, ln1_b, b1, b2, Q);

    ff_head_kernel<<<(Q + 31) / 32, 256>>>(hln_g, hln_b, hb1, hw2, hb2, Q, out);
}